// round 10
// baseline (speedup 1.0000x reference)
#include <cuda_runtime.h>
#include <cstdint>

// unpool expand: out quad [4i,4i+4) owned by input i;
//   out[4i + (idx[i]&3)] = in[i], other lanes 0. idx is int32. n = 8,388,608.
//
// Best-known memory shape (R3/R5): 4 elems/thread block-stride, coalesced
// scalar loads + float4 .cs stores. This version makes the grid persistent
// (1184 CTAs = 8 per SM on 148 SMs) with a grid-stride loop over tiles to
// remove wave-transition overhead and the ragged final wave.

#define ELEMS_PER_THREAD 4
#define THREADS 256
#define TILE (THREADS * ELEMS_PER_THREAD)   // 1024 elems per CTA-tile
#define GRID_CTAS 1184                       // 148 SMs * 8 CTAs

__device__ __forceinline__ void stcs_v4(float4* p, float4 q)
{
    asm volatile("st.global.cs.v4.f32 [%0], {%1, %2, %3, %4};"
                 :: "l"(p), "f"(q.x), "f"(q.y), "f"(q.z), "f"(q.w)
                 : "memory");
}

__global__ void __launch_bounds__(THREADS)
unpool_expand_kernel(const float* __restrict__ in,
                     const int* __restrict__ idx,
                     float4* __restrict__ out,
                     int n_tiles)
{
    for (int t = blockIdx.x; t < n_tiles; t += GRID_CTAS) {
        int base = t * TILE + threadIdx.x;

        int   off[ELEMS_PER_THREAD];
        float v[ELEMS_PER_THREAD];

        // Front-batched independent loads (MLP = 8 per thread).
#pragma unroll
        for (int k = 0; k < ELEMS_PER_THREAD; k++) {
            int i = base + k * THREADS;
            off[k] = __ldg(idx + i) & 3;
            v[k]   = __ldg(in + i);
        }

#pragma unroll
        for (int k = 0; k < ELEMS_PER_THREAD; k++) {
            int i = base + k * THREADS;
            float4 o = make_float4(0.f, 0.f, 0.f, 0.f);
            // constant-indexed branchless selects (no local memory)
            o.x = (off[k] == 0) ? v[k] : 0.f;
            o.y = (off[k] == 1) ? v[k] : 0.f;
            o.z = (off[k] == 2) ? v[k] : 0.f;
            o.w = (off[k] == 3) ? v[k] : 0.f;
            stcs_v4(out + i, o);   // 32 consecutive float4/warp = min wavefronts
        }
    }
}

extern "C" void kernel_launch(void* const* d_in, const int* in_sizes, int n_in,
                              void* d_out, int out_size)
{
    const float* in  = (const float*)d_in[0];
    const int*   idx = (const int*)d_in[1];
    float4*      out = (float4*)d_out;

    int n = in_sizes[0];           // 8,388,608 = 8192 * 1024 (exact tiles)
    int n_tiles = n / TILE;        // 8192
    unpool_expand_kernel<<<GRID_CTAS, THREADS>>>(in, idx, out, n_tiles);
}

// round 11
// speedup vs baseline: 1.1342x; 1.1342x over previous
#include <cuda_runtime.h>
#include <cstdint>

// unpool expand: out quad [4i,4i+4) owned by input i;
//   out[4i + (idx[i]&3)] = in[i], other lanes 0. idx is int32. n = 8,388,608.
//
// R3 memory shape (best benched): 4 elems/thread block-stride, coalesced
// scalar loads + float4 stores. NEW: write-through stores (st.global.wt)
// so the 128MB write stream reaches DRAM during the kernel (DRAM only ~58%
// busy then) instead of draining ~48MB of dirty L2 after kernel-end and
// serializing with the next graph replay.

#define ELEMS_PER_THREAD 4
#define THREADS 256

__device__ __forceinline__ void stwt_v4(float4* p, float4 q)
{
    asm volatile("st.global.wt.v4.f32 [%0], {%1, %2, %3, %4};"
                 :: "l"(p), "f"(q.x), "f"(q.y), "f"(q.z), "f"(q.w)
                 : "memory");
}

__global__ void __launch_bounds__(THREADS)
unpool_expand_kernel(const float* __restrict__ in,
                     const int* __restrict__ idx,
                     float4* __restrict__ out,
                     int n_in)
{
    int base = blockIdx.x * (THREADS * ELEMS_PER_THREAD) + threadIdx.x;

    int   off[ELEMS_PER_THREAD];
    float v[ELEMS_PER_THREAD];

    // Front-batched independent loads (MLP = 8 per thread).
#pragma unroll
    for (int k = 0; k < ELEMS_PER_THREAD; k++) {
        int i = base + k * THREADS;
        off[k] = __ldg(idx + i) & 3;
        v[k]   = __ldg(in + i);
    }

#pragma unroll
    for (int k = 0; k < ELEMS_PER_THREAD; k++) {
        int i = base + k * THREADS;
        float4 o;
        o.x = (off[k] == 0) ? v[k] : 0.f;
        o.y = (off[k] == 1) ? v[k] : 0.f;
        o.z = (off[k] == 2) ? v[k] : 0.f;
        o.w = (off[k] == 3) ? v[k] : 0.f;
        stwt_v4(out + i, o);   // 32 consecutive float4/warp = min wavefronts
    }
}

extern "C" void kernel_launch(void* const* d_in, const int* in_sizes, int n_in,
                              void* d_out, int out_size)
{
    const float* in  = (const float*)d_in[0];
    const int*   idx = (const int*)d_in[1];
    float4*      out = (float4*)d_out;

    int n = in_sizes[0];                         // 8,388,608
    int blocks = n / (THREADS * ELEMS_PER_THREAD);  // 8192
    unpool_expand_kernel<<<blocks, THREADS>>>(in, idx, out, n);
}